// round 10
// baseline (speedup 1.0000x reference)
#include <cuda_runtime.h>
#include <cuda_fp16.h>
#include <cstdint>

// DenseMRConv: out = x @ (Wt - Wb) + (max_k x_j) @ Wb + b
// k1: x -> fp16 shadow. k2: gather/hmax2 + packed f32x2 GEMM epilogue.
// MB=16 nodes/warp as 8 node-pairs; h staged pre-packed as u64{h[n0][d],h[n1][d]}
// in pair-major layout (conflict-free STS.128, uniform LDS.128 reads, no repack).

#define WPB 8
#define THREADS (WPB * 32)
#define D 64
#define KNBR 32
#define MB 16
#define NP 8            // node pairs per warp
#define MAXN 100000

__device__ __half2 g_xh[MAXN * (D / 2)];   // 12.8 MB fp16 shadow of x

// smem: Wp 32KB | hp 4KB/warp (8 pairs x 64 dims x u64)
#define WP_F4 2048
#define SMEM_BYTES (WP_F4 * 16 + WPB * 4096)

__global__ void __launch_bounds__(256) convert_kernel(const float2* __restrict__ x2, int n2) {
    const int e = blockIdx.x * 256 + threadIdx.x;
    if (e < n2) {
        const float2 v = x2[e];
        g_xh[e] = __floats2half2_rn(v.x, v.y);
    }
}

__device__ __forceinline__ void fma2(unsigned long long& d,
                                     unsigned long long a, unsigned long long b) {
    asm("fma.rn.f32x2 %0, %1, %2, %0;" : "+l"(d) : "l"(a), "l"(b));
}
__device__ __forceinline__ unsigned long long pack2(float v) {
    unsigned long long r;
    asm("mov.b64 %0, {%1, %1};" : "=l"(r) : "f"(v));
    return r;
}
__device__ __forceinline__ float2 unpack2(unsigned long long v) {
    float2 r;
    asm("mov.b64 {%0, %1}, %2;" : "=f"(r.x), "=f"(r.y) : "l"(v));
    return r;
}

// One epilogue pass over 64 dims (16 groups of 4). hp: pair-major u64 pairs.
__device__ __forceinline__ void epi_pass(const float4* __restrict__ Wp, int t0,
                                         const ulonglong2* __restrict__ hp, int lane,
                                         unsigned long long acc[NP][2]) {
    #pragma unroll 2
    for (int t = 0; t < 16; t++) {
        const float4 wA = Wp[(t0 + t) * 64 + lane];        // dims 4T,4T+1 cols 2l,2l+1
        const float4 wB = Wp[(t0 + t) * 64 + 32 + lane];   // dims 4T+2,4T+3
        const unsigned long long aAx = pack2(wA.x), aAy = pack2(wA.y);
        const unsigned long long aAz = pack2(wA.z), aAw = pack2(wA.w);
        const unsigned long long aBx = pack2(wB.x), aBy = pack2(wB.y);
        const unsigned long long aBz = pack2(wB.z), aBw = pack2(wB.w);
        #pragma unroll
        for (int p = 0; p < NP; p++) {
            const ulonglong2 U0 = hp[p * 32 + 2 * t];       // {v_4t, v_4t+1}
            const ulonglong2 U1 = hp[p * 32 + 2 * t + 1];   // {v_4t+2, v_4t+3}
            fma2(acc[p][0], U0.x, aAx); fma2(acc[p][1], U0.x, aAy);
            fma2(acc[p][0], U0.y, aAz); fma2(acc[p][1], U0.y, aAw);
            fma2(acc[p][0], U1.x, aBx); fma2(acc[p][1], U1.x, aBy);
            fma2(acc[p][0], U1.y, aBz); fma2(acc[p][1], U1.y, aBw);
        }
    }
}

__global__ void __launch_bounds__(THREADS, 3) mrconv_kernel(
    const float* __restrict__ x,
    const int* __restrict__ edge_index,
    const float* __restrict__ W,
    const float* __restrict__ b,
    float* __restrict__ out,
    int N)
{
    extern __shared__ float4 sm[];
    float4* __restrict__ Wp = sm;                       // W' permuted, 32 KB
    char* hpb = (char*)(sm + WP_F4);                    // 4 KB per warp

    const int tid  = threadIdx.x;
    const int warp = tid >> 5;
    const int lane = tid & 31;

    // Stage W': rows 0..63 = Wt - Wb, rows 64..127 = Wb.
    // Wp[t][h][l] = {W'[db][2l], W'[db][2l+1], W'[db+1][2l], W'[db+1][2l+1]}, db=4t+2h
    {
        const float2* W2 = (const float2*)W;
        for (int e = tid; e < WP_F4; e += THREADS) {
            const int l  = e & 31;
            const int h  = (e >> 5) & 1;
            const int t  = e >> 6;
            const int db = 4 * t + 2 * h;
            float2 a0 = W2[db * 32 + l];
            float2 a1 = W2[(db + 1) * 32 + l];
            if (db < 64) {
                const float2 s0 = W2[(db + 64) * 32 + l];
                const float2 s1 = W2[(db + 65) * 32 + l];
                a0.x -= s0.x; a0.y -= s0.y;
                a1.x -= s1.x; a1.y -= s1.y;
            }
            Wp[e] = make_float4(a0.x, a0.y, a1.x, a1.y);
        }
    }
    __syncthreads();

    const unsigned long long bb0 = pack2(b[2 * lane]);
    const unsigned long long bb1 = pack2(b[2 * lane + 1]);

    const float2* __restrict__ x2 = (const float2*)x;
    float2* __restrict__ out2     = (float2*)out;

    // per-warp staging: hp4 (write view), hpu (read view)
    float4*           hp4 = (float4*)(hpb + warp * 4096);
    const ulonglong2* hpu = (const ulonglong2*)(hpb + warp * 4096);

    const int gwarp  = blockIdx.x * WPB + warp;
    const int nwarps = gridDim.x * WPB;

    const __half2 hneg = __floats2half2_rn(-INFINITY, -INFINITY);

    for (int i0 = gwarp * MB; i0 < N; i0 += nwarps * MB) {
        // --- Stage x-pass h: pair-major, pre-packed node pairs ---
        #pragma unroll
        for (int p = 0; p < NP; p++) {
            const int iA = min(i0 + 2 * p, N - 1);
            const int iB = min(i0 + 2 * p + 1, N - 1);
            const float2 xa = x2[iA * (D / 2) + lane];
            const float2 xb = x2[iB * (D / 2) + lane];
            // 16B = u64{x_a[2l],x_b[2l]} | u64{x_a[2l+1],x_b[2l+1]}
            hp4[p * 32 + lane] = make_float4(xa.x, xb.x, xa.y, xb.y);
        }
        __syncwarp();

        // --- Gather: mx[m] = max_k x_j (fp16). idx via uniform __ldg (L1-hit). ---
        __half2 mxh[MB];
        #pragma unroll
        for (int m = 0; m < MB; m++) {
            mxh[m] = hneg;
            const int i = min(i0 + m, N - 1);
            const int4* ip = (const int4*)(edge_index + (size_t)i * KNBR);
            #pragma unroll 2
            for (int k4 = 0; k4 < 8; k4++) {
                const int4 jj = __ldg(ip + k4);
                mxh[m] = __hmax2(mxh[m], __ldcg(&g_xh[jj.x * (D / 2) + lane]));
                mxh[m] = __hmax2(mxh[m], __ldcg(&g_xh[jj.y * (D / 2) + lane]));
                mxh[m] = __hmax2(mxh[m], __ldcg(&g_xh[jj.z * (D / 2) + lane]));
                mxh[m] = __hmax2(mxh[m], __ldcg(&g_xh[jj.w * (D / 2) + lane]));
            }
        }

        unsigned long long acc[NP][2];
        #pragma unroll
        for (int p = 0; p < NP; p++) { acc[p][0] = bb0; acc[p][1] = bb1; }

        // --- Pass A: h = x, W' rows 0..63 ---
        epi_pass(Wp, 0, hpu, lane, acc);
        __syncwarp();

        // --- Stage mx-pass h ---
        #pragma unroll
        for (int p = 0; p < NP; p++) {
            const float2 ma = __half22float2(mxh[2 * p]);
            const float2 mb = __half22float2(mxh[2 * p + 1]);
            hp4[p * 32 + lane] = make_float4(ma.x, mb.x, ma.y, mb.y);
        }
        __syncwarp();

        // --- Pass B: h = mx, W' rows 64..127 ---
        epi_pass(Wp, 16, hpu, lane, acc);

        // --- Store: acc[p][c] = {out[n0][col_c], out[n1][col_c]} ---
        #pragma unroll
        for (int p = 0; p < NP; p++) {
            const float2 c0 = unpack2(acc[p][0]);
            const float2 c1 = unpack2(acc[p][1]);
            const int iA = i0 + 2 * p, iB = iA + 1;
            if (iA < N) out2[iA * (D / 2) + lane] = make_float2(c0.x, c1.x);
            if (iB < N) out2[iB * (D / 2) + lane] = make_float2(c0.y, c1.y);
        }
        __syncwarp();   // protect hp before next batch's staging
    }
}

extern "C" void kernel_launch(void* const* d_in, const int* in_sizes, int n_in,
                              void* d_out, int out_size) {
    const float* x  = (const float*)d_in[0];
    const int*   ei = (const int*)d_in[1];
    const float* W  = (const float*)d_in[2];
    const float* b  = (const float*)d_in[3];
    float* out = (float*)d_out;

    const int N = in_sizes[0] / D;
    const int n2 = N * (D / 2);

    static int smem_set = 0;
    if (!smem_set) {
        cudaFuncSetAttribute(mrconv_kernel,
                             cudaFuncAttributeMaxDynamicSharedMemorySize, SMEM_BYTES);
        smem_set = 1;
    }

    convert_kernel<<<(n2 + 255) / 256, 256>>>((const float2*)x, n2);

    // 64 KB smem -> 3 blocks/SM, 152 SMs
    const int grid = 456;
    mrconv_kernel<<<grid, THREADS, SMEM_BYTES>>>(x, ei, W, b, out, N);
}

// round 11
// speedup vs baseline: 1.2613x; 1.2613x over previous
#include <cuda_runtime.h>
#include <cuda_fp16.h>
#include <cstdint>

// DenseMRConv: out = x @ (Wt - Wb) + (max_k x_j) @ Wb + b
// k1: x -> fp16 shadow. k2: gather/hmax2 + packed f32x2 GEMM epilogue.
// MB=8 nodes/warp as 4 node-pairs (R9 occupancy point: 4 blocks/SM).
// h staged pre-packed pair-major u64{h[n0][d],h[n1][d]} -> conflict-free
// STS.128 writes, uniform LDS.128 reads, zero repack in the FMA loop.

#define WPB 8
#define THREADS (WPB * 32)
#define D 64
#define KNBR 32
#define MB 8
#define NP 4            // node pairs per warp
#define MAXN 100000

__device__ __half2 g_xh[MAXN * (D / 2)];   // 12.8 MB fp16 shadow of x

// smem: Wp 32KB | hp 2KB/warp (4 pairs x 64 dims x u64)
#define WP_F4 2048
#define SMEM_BYTES (WP_F4 * 16 + WPB * 2048)

__global__ void __launch_bounds__(256) convert_kernel(const float2* __restrict__ x2, int n2) {
    const int e = blockIdx.x * 256 + threadIdx.x;
    if (e < n2) {
        const float2 v = x2[e];
        g_xh[e] = __floats2half2_rn(v.x, v.y);
    }
}

__device__ __forceinline__ void fma2(unsigned long long& d,
                                     unsigned long long a, unsigned long long b) {
    asm("fma.rn.f32x2 %0, %1, %2, %0;" : "+l"(d) : "l"(a), "l"(b));
}
__device__ __forceinline__ unsigned long long pack2(float v) {
    unsigned long long r;
    asm("mov.b64 %0, {%1, %1};" : "=l"(r) : "f"(v));
    return r;
}
__device__ __forceinline__ float2 unpack2(unsigned long long v) {
    float2 r;
    asm("mov.b64 {%0, %1}, %2;" : "=f"(r.x), "=f"(r.y) : "l"(v));
    return r;
}

// One epilogue pass over 64 dims (16 groups of 4). hp: pair-major u64 pairs.
__device__ __forceinline__ void epi_pass(const float4* __restrict__ Wp, int t0,
                                         const ulonglong2* __restrict__ hp, int lane,
                                         unsigned long long acc[NP][2]) {
    #pragma unroll 2
    for (int t = 0; t < 16; t++) {
        const float4 wA = Wp[(t0 + t) * 64 + lane];        // dims 4t,4t+1 cols 2l,2l+1
        const float4 wB = Wp[(t0 + t) * 64 + 32 + lane];   // dims 4t+2,4t+3
        const unsigned long long aAx = pack2(wA.x), aAy = pack2(wA.y);
        const unsigned long long aAz = pack2(wA.z), aAw = pack2(wA.w);
        const unsigned long long aBx = pack2(wB.x), aBy = pack2(wB.y);
        const unsigned long long aBz = pack2(wB.z), aBw = pack2(wB.w);
        #pragma unroll
        for (int p = 0; p < NP; p++) {
            const ulonglong2 U0 = hp[p * 32 + 2 * t];       // {v_4t, v_4t+1}
            const ulonglong2 U1 = hp[p * 32 + 2 * t + 1];   // {v_4t+2, v_4t+3}
            fma2(acc[p][0], U0.x, aAx); fma2(acc[p][1], U0.x, aAy);
            fma2(acc[p][0], U0.y, aAz); fma2(acc[p][1], U0.y, aAw);
            fma2(acc[p][0], U1.x, aBx); fma2(acc[p][1], U1.x, aBy);
            fma2(acc[p][0], U1.y, aBz); fma2(acc[p][1], U1.y, aBw);
        }
    }
}

__global__ void __launch_bounds__(THREADS, 4) mrconv_kernel(
    const float* __restrict__ x,
    const int* __restrict__ edge_index,
    const float* __restrict__ W,
    const float* __restrict__ b,
    float* __restrict__ out,
    int N)
{
    extern __shared__ float4 sm[];
    float4* __restrict__ Wp = sm;                       // W' permuted, 32 KB
    char* hpb = (char*)(sm + WP_F4);                    // 2 KB per warp

    const int tid  = threadIdx.x;
    const int warp = tid >> 5;
    const int lane = tid & 31;

    // Stage W': rows 0..63 = Wt - Wb, rows 64..127 = Wb.
    // Wp[t][h][l] = {W'[db][2l], W'[db][2l+1], W'[db+1][2l], W'[db+1][2l+1]}, db=4t+2h
    {
        const float2* W2 = (const float2*)W;
        for (int e = tid; e < WP_F4; e += THREADS) {
            const int l  = e & 31;
            const int h  = (e >> 5) & 1;
            const int t  = e >> 6;
            const int db = 4 * t + 2 * h;
            float2 a0 = W2[db * 32 + l];
            float2 a1 = W2[(db + 1) * 32 + l];
            if (db < 64) {
                const float2 s0 = W2[(db + 64) * 32 + l];
                const float2 s1 = W2[(db + 65) * 32 + l];
                a0.x -= s0.x; a0.y -= s0.y;
                a1.x -= s1.x; a1.y -= s1.y;
            }
            Wp[e] = make_float4(a0.x, a0.y, a1.x, a1.y);
        }
    }
    __syncthreads();

    const unsigned long long bb0 = pack2(b[2 * lane]);
    const unsigned long long bb1 = pack2(b[2 * lane + 1]);

    const float2* __restrict__ x2 = (const float2*)x;
    float2* __restrict__ out2     = (float2*)out;

    float4*           hp4 = (float4*)(hpb + warp * 2048);
    const ulonglong2* hpu = (const ulonglong2*)(hpb + warp * 2048);

    const int gwarp  = blockIdx.x * WPB + warp;
    const int nwarps = gridDim.x * WPB;

    const __half2 hneg = __floats2half2_rn(-INFINITY, -INFINITY);

    for (int i0 = gwarp * MB; i0 < N; i0 += nwarps * MB) {
        // --- Stage x-pass h: pair-major, pre-packed node pairs (conflict-free) ---
        #pragma unroll
        for (int p = 0; p < NP; p++) {
            const int iA = min(i0 + 2 * p, N - 1);
            const int iB = min(i0 + 2 * p + 1, N - 1);
            const float2 xa = x2[iA * (D / 2) + lane];
            const float2 xb = x2[iB * (D / 2) + lane];
            // 16B = u64{x_a[2l],x_b[2l]} | u64{x_a[2l+1],x_b[2l+1]}
            hp4[p * 32 + lane] = make_float4(xa.x, xb.x, xa.y, xb.y);
        }
        __syncwarp();

        // --- Gather: mx[m] = max_k x_j (fp16). idx via uniform __ldg int4. ---
        __half2 mxh[MB];
        #pragma unroll
        for (int m = 0; m < MB; m++) {
            mxh[m] = hneg;
            const int i = min(i0 + m, N - 1);
            const int4* ip = (const int4*)(edge_index + (size_t)i * KNBR);
            #pragma unroll 4
            for (int k4 = 0; k4 < 8; k4++) {
                const int4 jj = __ldg(ip + k4);
                mxh[m] = __hmax2(mxh[m], __ldcg(&g_xh[jj.x * (D / 2) + lane]));
                mxh[m] = __hmax2(mxh[m], __ldcg(&g_xh[jj.y * (D / 2) + lane]));
                mxh[m] = __hmax2(mxh[m], __ldcg(&g_xh[jj.z * (D / 2) + lane]));
                mxh[m] = __hmax2(mxh[m], __ldcg(&g_xh[jj.w * (D / 2) + lane]));
            }
        }

        unsigned long long acc[NP][2];
        #pragma unroll
        for (int p = 0; p < NP; p++) { acc[p][0] = bb0; acc[p][1] = bb1; }

        // --- Pass A: h = x, W' rows 0..63 ---
        epi_pass(Wp, 0, hpu, lane, acc);
        __syncwarp();

        // --- Stage mx-pass h ---
        #pragma unroll
        for (int p = 0; p < NP; p++) {
            const float2 ma = __half22float2(mxh[2 * p]);
            const float2 mb = __half22float2(mxh[2 * p + 1]);
            hp4[p * 32 + lane] = make_float4(ma.x, mb.x, ma.y, mb.y);
        }
        __syncwarp();

        // --- Pass B: h = mx, W' rows 64..127 ---
        epi_pass(Wp, 16, hpu, lane, acc);

        // --- Store: acc[p][c] = {out[n0][col_c], out[n1][col_c]} ---
        #pragma unroll
        for (int p = 0; p < NP; p++) {
            const float2 c0 = unpack2(acc[p][0]);
            const float2 c1 = unpack2(acc[p][1]);
            const int iA = i0 + 2 * p, iB = iA + 1;
            if (iA < N) out2[iA * (D / 2) + lane] = make_float2(c0.x, c1.x);
            if (iB < N) out2[iB * (D / 2) + lane] = make_float2(c0.y, c1.y);
        }
        __syncwarp();   // protect hp before next batch's staging
    }
}

extern "C" void kernel_launch(void* const* d_in, const int* in_sizes, int n_in,
                              void* d_out, int out_size) {
    const float* x  = (const float*)d_in[0];
    const int*   ei = (const int*)d_in[1];
    const float* W  = (const float*)d_in[2];
    const float* b  = (const float*)d_in[3];
    float* out = (float*)d_out;

    const int N = in_sizes[0] / D;
    const int n2 = N * (D / 2);

    static int smem_set = 0;
    if (!smem_set) {
        cudaFuncSetAttribute(mrconv_kernel,
                             cudaFuncAttributeMaxDynamicSharedMemorySize, SMEM_BYTES);
        smem_set = 1;
    }

    convert_kernel<<<(n2 + 255) / 256, 256>>>((const float2*)x, n2);

    // 48 KB smem, <=64 regs -> 4 blocks/SM, 152 SMs
    const int grid = 608;
    mrconv_kernel<<<grid, THREADS, SMEM_BYTES>>>(x, ei, W, b, out, N);
}

// round 13
// speedup vs baseline: 1.3663x; 1.0832x over previous
#include <cuda_runtime.h>
#include <cuda_fp16.h>
#include <cstdint>

// DenseMRConv: out = x @ (Wt - Wb) + (max_k x_j) @ Wb + b
// k1: x -> fp16 shadow. k2: warp-cooperative wide gather (LDG.128 = 4 rows)
// + packed f32x2 GEMM epilogue. MB=8 nodes/warp as 4 pairs, 4 blocks/SM.

#define WPB 8
#define THREADS (WPB * 32)
#define D 64
#define KNBR 32
#define MB 8
#define NP 4
#define MAXN 100000

__device__ __half2 g_xh[MAXN * (D / 2)];   // 12.8 MB fp16 shadow of x

#define WP_F4 2048
#define SMEM_BYTES (WP_F4 * 16 + WPB * 2048)

__global__ void __launch_bounds__(256) convert_kernel(const float2* __restrict__ x2, int n2) {
    const int e = blockIdx.x * 256 + threadIdx.x;
    if (e < n2) {
        const float2 v = x2[e];
        g_xh[e] = __floats2half2_rn(v.x, v.y);
    }
}

__device__ __forceinline__ void fma2(unsigned long long& d,
                                     unsigned long long a, unsigned long long b) {
    asm("fma.rn.f32x2 %0, %1, %2, %0;" : "+l"(d) : "l"(a), "l"(b));
}
__device__ __forceinline__ unsigned long long pack2(float v) {
    unsigned long long r;
    asm("mov.b64 %0, {%1, %1};" : "=l"(r) : "f"(v));
    return r;
}
__device__ __forceinline__ float2 unpack2(unsigned long long v) {
    float2 r;
    asm("mov.b64 {%0, %1}, %2;" : "=f"(r.x), "=f"(r.y) : "l"(v));
    return r;
}
__device__ __forceinline__ __half2 hshflx(__half2 v, int m) {
    const unsigned u = __shfl_xor_sync(0xffffffffu, *(const unsigned*)&v, m);
    return *(const __half2*)&u;
}

// One epilogue pass over 64 dims. hp: pair-major u64{h[n0][d],h[n1][d]}.
__device__ __forceinline__ void epi_pass(const float4* __restrict__ Wp, int t0,
                                         const ulonglong2* __restrict__ hp, int lane,
                                         unsigned long long acc[NP][2]) {
    #pragma unroll 2
    for (int t = 0; t < 16; t++) {
        const float4 wA = Wp[(t0 + t) * 64 + lane];        // dims 4t,4t+1 cols 2l,2l+1
        const float4 wB = Wp[(t0 + t) * 64 + 32 + lane];   // dims 4t+2,4t+3
        const unsigned long long aAx = pack2(wA.x), aAy = pack2(wA.y);
        const unsigned long long aAz = pack2(wA.z), aAw = pack2(wA.w);
        const unsigned long long aBx = pack2(wB.x), aBy = pack2(wB.y);
        const unsigned long long aBz = pack2(wB.z), aBw = pack2(wB.w);
        #pragma unroll
        for (int p = 0; p < NP; p++) {
            const ulonglong2 U0 = hp[p * 32 + 2 * t];
            const ulonglong2 U1 = hp[p * 32 + 2 * t + 1];
            fma2(acc[p][0], U0.x, aAx); fma2(acc[p][1], U0.x, aAy);
            fma2(acc[p][0], U0.y, aAz); fma2(acc[p][1], U0.y, aAw);
            fma2(acc[p][0], U1.x, aBx); fma2(acc[p][1], U1.x, aBy);
            fma2(acc[p][0], U1.y, aBz); fma2(acc[p][1], U1.y, aBw);
        }
    }
}

__global__ void __launch_bounds__(THREADS, 4) mrconv_kernel(
    const float* __restrict__ x,
    const int* __restrict__ edge_index,
    const float* __restrict__ W,
    const float* __restrict__ b,
    float* __restrict__ out,
    int N)
{
    extern __shared__ float4 sm[];
    float4* __restrict__ Wp = sm;                       // W' permuted, 32 KB
    char* hpb = (char*)(sm + WP_F4);                    // 2 KB per warp

    const int tid  = threadIdx.x;
    const int warp = tid >> 5;
    const int lane = tid & 31;

    // Stage W': rows 0..63 = Wt - Wb, rows 64..127 = Wb.
    {
        const float2* W2 = (const float2*)W;
        for (int e = tid; e < WP_F4; e += THREADS) {
            const int l  = e & 31;
            const int h  = (e >> 5) & 1;
            const int t  = e >> 6;
            const int db = 4 * t + 2 * h;
            float2 a0 = W2[db * 32 + l];
            float2 a1 = W2[(db + 1) * 32 + l];
            if (db < 64) {
                const float2 s0 = W2[(db + 64) * 32 + l];
                const float2 s1 = W2[(db + 65) * 32 + l];
                a0.x -= s0.x; a0.y -= s0.y;
                a1.x -= s1.x; a1.y -= s1.y;
            }
            Wp[e] = make_float4(a0.x, a0.y, a1.x, a1.y);
        }
    }
    __syncthreads();

    const unsigned long long bb0 = pack2(b[2 * lane]);
    const unsigned long long bb1 = pack2(b[2 * lane + 1]);

    const float2* __restrict__ x2 = (const float2*)x;
    float2* __restrict__ out2     = (float2*)out;

    float4*           hp4 = (float4*)(hpb + warp * 2048);
    const ulonglong2* hpu = (const ulonglong2*)(hpb + warp * 2048);

    const int gwarp  = blockIdx.x * WPB + warp;
    const int nwarps = gridDim.x * WPB;

    const __half2 hneg = __floats2half2_rn(-INFINITY, -INFINITY);
    const int sub2 = (lane >> 3) & 1;        // neighbor-parity sub-group
    const int h16  = lane & 16;              // node half: 0 = node A, 16 = node B
    const int half = h16 >> 4;               // 0 / 1
    const int bl   = lane & 7;               // 16B slice within row (dims 8bl..8bl+7)

    for (int i0 = gwarp * MB; i0 < N; i0 += nwarps * MB) {
        // --- Phase 1: cooperative gather + stage mx pairs (pair-major u64) ---
        #pragma unroll
        for (int p = 0; p < NP; p++) {
            const int iA = min(i0 + 2 * p, N - 1);
            const int iB = min(i0 + 2 * p + 1, N - 1);
            const int rA = edge_index[iA * KNBR + lane];
            const int rB = edge_index[iB * KNBR + lane];
            // s0: lanes0-15 = A[0..15], lanes16-31 = B[0..15]
            // s1: lanes0-15 = A[16..31], lanes16-31 = B[16..31]
            const int blo = __shfl_sync(0xffffffffu, rB, lane & 15);
            const int ahi = __shfl_sync(0xffffffffu, rA, 16 | (lane & 15));
            const int s0 = (lane < 16) ? rA : blo;
            const int s1 = (lane < 16) ? ahi : rB;

            __half2 m0 = hneg, m1 = hneg, m2 = hneg, m3 = hneg;
            #pragma unroll
            for (int t = 0; t < 16; t++) {
                const int kk  = 2 * t + sub2;               // neighbor slot
                const int src = (kk & 15) | h16;
                const int j   = __shfl_sync(0xffffffffu, (t < 8) ? s0 : s1, src);
                const float4 v = __ldcg((const float4*)(g_xh + j * (D / 2)) + bl);
                const __half2* q = (const __half2*)&v;
                m0 = __hmax2(m0, q[0]); m1 = __hmax2(m1, q[1]);
                m2 = __hmax2(m2, q[2]); m3 = __hmax2(m3, q[3]);
            }
            // reduce across sub2 partner (lane ^ 8): full max over 32 neighbors
            m0 = __hmax2(m0, hshflx(m0, 8)); m1 = __hmax2(m1, hshflx(m1, 8));
            m2 = __hmax2(m2, hshflx(m2, 8)); m3 = __hmax2(m3, hshflx(m3, 8));

            // Exchange groups chosen by sub2 ONLY (bit4-invariant), so the
            // xor-16 partner holds the SAME dim group for the other node.
            const __half2 ga = sub2 ? m2 : m0;   // group 2*sub2
            const __half2 gb = sub2 ? m3 : m1;   // group 2*sub2+1
            const __half2 ga_o = hshflx(ga, 16);
            const __half2 gb_o = hshflx(gb, 16);
            // This lane stages group g = 2*sub2 + half (entry 4*bl + g):
            //   half==0 lane: group 2*sub2   -> node-A value = ga, node-B = ga_o
            //   half==1 lane: group 2*sub2+1 -> node-A value = gb_o, node-B = gb
            const __half2 vA = half ? gb_o : ga;
            const __half2 vB = half ? gb   : ga_o;
            const float2 fa = __half22float2(vA);
            const float2 fb = __half22float2(vB);
            hp4[p * 32 + 4 * bl + 2 * sub2 + half] = make_float4(fa.x, fb.x, fa.y, fb.y);
        }
        __syncwarp();

        unsigned long long acc[NP][2];
        #pragma unroll
        for (int p = 0; p < NP; p++) { acc[p][0] = bb0; acc[p][1] = bb1; }

        // --- Pass B: h = mx, W' rows 64..127 ---
        epi_pass(Wp, 16, hpu, lane, acc);
        __syncwarp();

        // --- Stage x pairs (lane owns dims 2l,2l+1) ---
        #pragma unroll
        for (int p = 0; p < NP; p++) {
            const int iA = min(i0 + 2 * p, N - 1);
            const int iB = min(i0 + 2 * p + 1, N - 1);
            const float2 xa = x2[iA * (D / 2) + lane];
            const float2 xb = x2[iB * (D / 2) + lane];
            hp4[p * 32 + lane] = make_float4(xa.x, xb.x, xa.y, xb.y);
        }
        __syncwarp();

        // --- Pass A: h = x, W' rows 0..63 ---
        epi_pass(Wp, 0, hpu, lane, acc);

        // --- Store ---
        #pragma unroll
        for (int p = 0; p < NP; p++) {
            const float2 c0 = unpack2(acc[p][0]);
            const float2 c1 = unpack2(acc[p][1]);
            const int iA = i0 + 2 * p, iB = iA + 1;
            if (iA < N) out2[iA * (D / 2) + lane] = make_float2(c0.x, c1.x);
            if (iB < N) out2[iB * (D / 2) + lane] = make_float2(c0.y, c1.y);
        }
        __syncwarp();
    }
}

extern "C" void kernel_launch(void* const* d_in, const int* in_sizes, int n_in,
                              void* d_out, int out_size) {
    const float* x  = (const float*)d_in[0];
    const int*   ei = (const int*)d_in[1];
    const float* W  = (const float*)d_in[2];
    const float* b  = (const float*)d_in[3];
    float* out = (float*)d_out;

    const int N = in_sizes[0] / D;
    const int n2 = N * (D / 2);

    static int smem_set = 0;
    if (!smem_set) {
        cudaFuncSetAttribute(mrconv_kernel,
                             cudaFuncAttributeMaxDynamicSharedMemorySize, SMEM_BYTES);
        smem_set = 1;
    }

    convert_kernel<<<(n2 + 255) / 256, 256>>>((const float2*)x, n2);

    // 48 KB smem, <=64 regs -> 4 blocks/SM, 152 SMs
    const int grid = 608;
    mrconv_kernel<<<grid, THREADS, SMEM_BYTES>>>(x, ei, W, b, out, N);
}